// round 1
// baseline (speedup 1.0000x reference)
#include <cuda_runtime.h>
#include <math.h>

#define N_TOK 4096
#define D_DIM 512
#define E_NUM 8
#define H_DIM 256

// ---------------- scratch (static device globals; no allocation) -------------
__device__ int   g_counts[E_NUM];
__device__ int   g_bucket_tok[E_NUM * N_TOK];   // packed tok*2 + slot
__device__ float g_bucket_scr[E_NUM * N_TOK];   // routing prob for that slot
__device__ float g_h1[N_TOK * H_DIM];           // shared-expert hidden
__device__ float g_hr[N_TOK * 2 * H_DIM];       // routed hidden, row = tok*2+slot
__device__ float g_yb[N_TOK * 2 * D_DIM];       // routed down-proj rows

// ---------------- reset ------------------------------------------------------
__global__ void k_reset() {
    if (threadIdx.x < E_NUM) g_counts[threadIdx.x] = 0;
}

// ---------------- router: warp per token ------------------------------------
__global__ void __launch_bounds__(256) k_router(const float* __restrict__ x,
                                                const float* __restrict__ router) {
    int warp = (blockIdx.x * blockDim.x + threadIdx.x) >> 5;
    int lane = threadIdx.x & 31;
    if (warp >= N_TOK) return;
    const float* xr = x + (size_t)warp * D_DIM;
    float acc[E_NUM];
#pragma unroll
    for (int e = 0; e < E_NUM; e++) acc[e] = 0.f;
    for (int d = lane; d < D_DIM; d += 32) {
        float xv = xr[d];
        const float* rr = router + (size_t)d * E_NUM;
#pragma unroll
        for (int e = 0; e < E_NUM; e++) acc[e] += xv * rr[e];
    }
#pragma unroll
    for (int e = 0; e < E_NUM; e++) {
#pragma unroll
        for (int off = 16; off; off >>= 1)
            acc[e] += __shfl_xor_sync(0xffffffffu, acc[e], off);
    }
    if (lane == 0) {
        float mx = acc[0];
#pragma unroll
        for (int e = 1; e < E_NUM; e++) mx = fmaxf(mx, acc[e]);
        float p[E_NUM], s = 0.f;
#pragma unroll
        for (int e = 0; e < E_NUM; e++) { p[e] = expf(acc[e] - mx); s += p[e]; }
        float inv = 1.f / s;
#pragma unroll
        for (int e = 0; e < E_NUM; e++) p[e] *= inv;
        // top-2, lowest index wins ties (matches top_k)
        int e0 = 0;
#pragma unroll
        for (int e = 1; e < E_NUM; e++) if (p[e] > p[e0]) e0 = e;
        int e1 = (e0 == 0) ? 1 : 0;
#pragma unroll
        for (int e = 0; e < E_NUM; e++)
            if (e != e0 && e != e1 && p[e] > p[e1]) e1 = e;
        int pos0 = atomicAdd(&g_counts[e0], 1);
        g_bucket_tok[e0 * N_TOK + pos0] = warp * 2 + 0;
        g_bucket_scr[e0 * N_TOK + pos0] = p[e0];
        int pos1 = atomicAdd(&g_counts[e1], 1);
        g_bucket_tok[e1 * N_TOK + pos1] = warp * 2 + 1;
        g_bucket_scr[e1 * N_TOK + pos1] = p[e1];
    }
}

// ---------------- fused gate+up GEMM + SiLU ---------------------------------
// C tile 64x64, K-slice 16, 256 threads, 4x4 microtile per thread.
template <bool ROUTED>
__global__ void __launch_bounds__(256) k_gateup(const float* __restrict__ X,
                                                const float* __restrict__ Wg_,
                                                const float* __restrict__ Wu_) {
    __shared__ float As[16][68];   // [k][m], padded
    __shared__ float Bg[16][64];   // [k][n]
    __shared__ float Bu[16][64];

    const int e    = ROUTED ? blockIdx.z : 0;
    const int M    = ROUTED ? g_counts[e] : N_TOK;
    const int row0 = blockIdx.x * 64;
    if (row0 >= M) return;
    const int col0 = blockIdx.y * 64;
    const float* Wg = Wg_ + (ROUTED ? (size_t)e * D_DIM * H_DIM : 0);
    const float* Wu = Wu_ + (ROUTED ? (size_t)e * D_DIM * H_DIM : 0);

    const int tid = threadIdx.x;
    const int am = tid >> 2, akq = tid & 3;   // A loader: row am, k-quad akq
    const int bk = tid >> 4, bnq = tid & 15;  // B loader: k row bk, n-quad bnq
    const int tr = tid >> 4, tc = tid & 15;   // compute microtile coords

    int arow = row0 + am;
    bool avalid = arow < M;
    int tok = 0;
    if (ROUTED) { if (avalid) tok = g_bucket_tok[e * N_TOK + arow] >> 1; }
    else tok = avalid ? arow : 0;
    const float* Arow = X + (size_t)tok * D_DIM;

    float accg[4][4] = {}, accu[4][4] = {};

    for (int k0 = 0; k0 < D_DIM; k0 += 16) {
        float4 av = avalid ? *(const float4*)(Arow + k0 + akq * 4)
                           : make_float4(0.f, 0.f, 0.f, 0.f);
        As[akq * 4 + 0][am] = av.x;
        As[akq * 4 + 1][am] = av.y;
        As[akq * 4 + 2][am] = av.z;
        As[akq * 4 + 3][am] = av.w;
        *(float4*)&Bg[bk][bnq * 4] =
            *(const float4*)(Wg + (size_t)(k0 + bk) * H_DIM + col0 + bnq * 4);
        *(float4*)&Bu[bk][bnq * 4] =
            *(const float4*)(Wu + (size_t)(k0 + bk) * H_DIM + col0 + bnq * 4);
        __syncthreads();
#pragma unroll
        for (int k = 0; k < 16; k++) {
            float4 a  = *(const float4*)&As[k][tr * 4];
            float4 b0 = *(const float4*)&Bg[k][tc * 4];
            float4 b1 = *(const float4*)&Bu[k][tc * 4];
            float ar[4]  = {a.x, a.y, a.z, a.w};
            float bgr[4] = {b0.x, b0.y, b0.z, b0.w};
            float bur[4] = {b1.x, b1.y, b1.z, b1.w};
#pragma unroll
            for (int i = 0; i < 4; i++)
#pragma unroll
                for (int j = 0; j < 4; j++) {
                    accg[i][j] += ar[i] * bgr[j];
                    accu[i][j] += ar[i] * bur[j];
                }
        }
        __syncthreads();
    }

#pragma unroll
    for (int i = 0; i < 4; i++) {
        int r = row0 + tr * 4 + i;
        if (r >= M) continue;
        size_t obase;
        float* optr;
        if (ROUTED) {
            int tok2 = g_bucket_tok[e * N_TOK + r];
            obase = (size_t)tok2 * H_DIM; optr = g_hr;
        } else {
            obase = (size_t)r * H_DIM; optr = g_h1;
        }
        float4 hv;
        float hj[4];
#pragma unroll
        for (int j = 0; j < 4; j++) {
            float g = accg[i][j], u = accu[i][j];
            hj[j] = (g / (1.f + expf(-g))) * u;   // silu(g)*u
        }
        hv.x = hj[0]; hv.y = hj[1]; hv.z = hj[2]; hv.w = hj[3];
        *(float4*)(optr + obase + col0 + tc * 4) = hv;
    }
}

// ---------------- down-proj GEMM --------------------------------------------
template <bool ROUTED>
__global__ void __launch_bounds__(256) k_down(const float* __restrict__ Wd_,
                                              float* __restrict__ Out) {
    __shared__ float As[16][68];
    __shared__ float Bs[16][64];

    const int e    = ROUTED ? blockIdx.z : 0;
    const int M    = ROUTED ? g_counts[e] : N_TOK;
    const int row0 = blockIdx.x * 64;
    if (row0 >= M) return;
    const int col0 = blockIdx.y * 64;
    const float* Wd = Wd_ + (ROUTED ? (size_t)e * H_DIM * D_DIM : 0);

    const int tid = threadIdx.x;
    const int am = tid >> 2, akq = tid & 3;
    const int bk = tid >> 4, bnq = tid & 15;
    const int tr = tid >> 4, tc = tid & 15;

    int arow = row0 + am;
    bool avalid = arow < M;
    size_t abase = 0;
    const float* Hin;
    if (ROUTED) {
        int tok2 = avalid ? g_bucket_tok[e * N_TOK + arow] : 0;
        abase = (size_t)tok2 * H_DIM; Hin = g_hr;
    } else {
        abase = (size_t)(avalid ? arow : 0) * H_DIM; Hin = g_h1;
    }

    float acc[4][4] = {};

    for (int k0 = 0; k0 < H_DIM; k0 += 16) {
        float4 av = avalid ? *(const float4*)(Hin + abase + k0 + akq * 4)
                           : make_float4(0.f, 0.f, 0.f, 0.f);
        As[akq * 4 + 0][am] = av.x;
        As[akq * 4 + 1][am] = av.y;
        As[akq * 4 + 2][am] = av.z;
        As[akq * 4 + 3][am] = av.w;
        *(float4*)&Bs[bk][bnq * 4] =
            *(const float4*)(Wd + (size_t)(k0 + bk) * D_DIM + col0 + bnq * 4);
        __syncthreads();
#pragma unroll
        for (int k = 0; k < 16; k++) {
            float4 a = *(const float4*)&As[k][tr * 4];
            float4 b = *(const float4*)&Bs[k][tc * 4];
            float ar[4] = {a.x, a.y, a.z, a.w};
            float br[4] = {b.x, b.y, b.z, b.w};
#pragma unroll
            for (int i = 0; i < 4; i++)
#pragma unroll
                for (int j = 0; j < 4; j++)
                    acc[i][j] += ar[i] * br[j];
        }
        __syncthreads();
    }

#pragma unroll
    for (int i = 0; i < 4; i++) {
        int r = row0 + tr * 4 + i;
        if (r >= M) continue;
        float scr = 1.f;
        size_t obase;
        float* optr;
        if (ROUTED) {
            int tok2 = g_bucket_tok[e * N_TOK + r];
            scr   = g_bucket_scr[e * N_TOK + r];
            obase = (size_t)tok2 * D_DIM; optr = g_yb;
        } else {
            obase = (size_t)r * D_DIM; optr = Out;
        }
        float4 v;
        v.x = scr * acc[i][0]; v.y = scr * acc[i][1];
        v.z = scr * acc[i][2]; v.w = scr * acc[i][3];
        *(float4*)(optr + obase + col0 + tc * 4) = v;
    }
}

// ---------------- final combine ---------------------------------------------
__global__ void __launch_bounds__(256) k_final(float* __restrict__ Out) {
    int i = (blockIdx.x * blockDim.x + threadIdx.x) * 4;
    if (i >= N_TOK * D_DIM) return;
    int n = i / D_DIM, d = i % D_DIM;
    float4 o  = *(float4*)(Out + i);
    float4 y0 = *(const float4*)(g_yb + (size_t)(2 * n) * D_DIM + d);
    float4 y1 = *(const float4*)(g_yb + (size_t)(2 * n + 1) * D_DIM + d);
    o.x += y0.x + y1.x;
    o.y += y0.y + y1.y;
    o.z += y0.z + y1.z;
    o.w += y0.w + y1.w;
    *(float4*)(Out + i) = o;
}

// ---------------- launch -----------------------------------------------------
extern "C" void kernel_launch(void* const* d_in, const int* in_sizes, int n_in,
                              void* d_out, int out_size) {
    const float* x           = (const float*)d_in[0];
    const float* router      = (const float*)d_in[1];
    const float* shared_gate = (const float*)d_in[2];
    const float* shared_up   = (const float*)d_in[3];
    const float* shared_down = (const float*)d_in[4];
    const float* W_gate      = (const float*)d_in[5];
    const float* W_up        = (const float*)d_in[6];
    const float* W_down      = (const float*)d_in[7];
    float* out = (float*)d_out;

    (void)in_sizes; (void)n_in; (void)out_size;

    k_reset<<<1, 32>>>();
    k_router<<<N_TOK / 8, 256>>>(x, router);

    // shared expert
    {
        dim3 g(N_TOK / 64, H_DIM / 64, 1);
        k_gateup<false><<<g, 256>>>(x, shared_gate, shared_up);
    }
    {
        dim3 g(N_TOK / 64, D_DIM / 64, 1);
        k_down<false><<<g, 256>>>(shared_down, out);
    }

    // routed experts (grid sized for worst case; tiles past count exit early)
    {
        dim3 g(N_TOK / 64, H_DIM / 64, E_NUM);
        k_gateup<true><<<g, 256>>>(x, W_gate, W_up);
    }
    {
        dim3 g(N_TOK / 64, D_DIM / 64, E_NUM);
        k_down<true><<<g, 256>>>(W_down, out);
    }

    k_final<<<(N_TOK * D_DIM / 4 + 255) / 256, 256>>>(out);
}

// round 5
// speedup vs baseline: 1.6139x; 1.6139x over previous
#include <cuda_runtime.h>
#include <cuda_bf16.h>
#include <math.h>
#include <stdint.h>

#define N_TOK 4096
#define D_DIM 512
#define E_NUM 8
#define H_DIM 256

// ---------------- scratch (static device globals; no allocation) -------------
__device__ int   g_counts[E_NUM];
__device__ int   g_bucket_tok[E_NUM * N_TOK];   // packed tok*2 + slot
__device__ float g_bucket_scr[E_NUM * N_TOK];

// bf16 hi/lo splits
__device__ __nv_bfloat16 g_xh[N_TOK * D_DIM],  g_xl[N_TOK * D_DIM];
__device__ __nv_bfloat16 g_sgh[D_DIM * H_DIM], g_sgl[D_DIM * H_DIM];
__device__ __nv_bfloat16 g_suh[D_DIM * H_DIM], g_sul[D_DIM * H_DIM];
__device__ __nv_bfloat16 g_sdh[H_DIM * D_DIM], g_sdl[H_DIM * D_DIM];
__device__ __nv_bfloat16 g_Wgh[E_NUM * D_DIM * H_DIM], g_Wgl[E_NUM * D_DIM * H_DIM];
__device__ __nv_bfloat16 g_Wuh[E_NUM * D_DIM * H_DIM], g_Wul[E_NUM * D_DIM * H_DIM];
__device__ __nv_bfloat16 g_Wdh[E_NUM * H_DIM * D_DIM], g_Wdl[E_NUM * H_DIM * D_DIM];
// hidden activations (split for next GEMM)
__device__ __nv_bfloat16 g_h1h[N_TOK * H_DIM], g_h1l[N_TOK * H_DIM];
__device__ __nv_bfloat16 g_hrh[N_TOK * 2 * H_DIM], g_hrl[N_TOK * 2 * H_DIM];
// routed down-proj output rows (fp32)
__device__ float g_yb[N_TOK * 2 * D_DIM];

// ---------------- reset ------------------------------------------------------
__global__ void k_reset() {
    if (threadIdx.x < E_NUM) g_counts[threadIdx.x] = 0;
}

// ---------------- fp32 -> bf16 hi/lo split -----------------------------------
__global__ void __launch_bounds__(256) k_split(const float* __restrict__ src,
                                               int which, int n) {
    int i = blockIdx.x * blockDim.x + threadIdx.x;
    if (i >= n) return;
    __nv_bfloat16 *dh, *dl;
    switch (which) {
        case 0: dh = g_xh;  dl = g_xl;  break;
        case 1: dh = g_sgh; dl = g_sgl; break;
        case 2: dh = g_suh; dl = g_sul; break;
        case 3: dh = g_sdh; dl = g_sdl; break;
        case 4: dh = g_Wgh; dl = g_Wgl; break;
        case 5: dh = g_Wuh; dl = g_Wul; break;
        default: dh = g_Wdh; dl = g_Wdl; break;
    }
    float v = src[i];
    __nv_bfloat16 h = __float2bfloat16(v);
    dh[i] = h;
    dl[i] = __float2bfloat16(v - __bfloat162float(h));
}

// ---------------- router: warp per token ------------------------------------
__global__ void __launch_bounds__(256) k_router(const float* __restrict__ x,
                                                const float* __restrict__ router) {
    int warp = (blockIdx.x * blockDim.x + threadIdx.x) >> 5;
    int lane = threadIdx.x & 31;
    if (warp >= N_TOK) return;
    const float* xr = x + (size_t)warp * D_DIM;
    float acc[E_NUM];
#pragma unroll
    for (int e = 0; e < E_NUM; e++) acc[e] = 0.f;
    for (int d = lane; d < D_DIM; d += 32) {
        float xv = xr[d];
        const float* rr = router + (size_t)d * E_NUM;
#pragma unroll
        for (int e = 0; e < E_NUM; e++) acc[e] += xv * rr[e];
    }
#pragma unroll
    for (int e = 0; e < E_NUM; e++) {
#pragma unroll
        for (int off = 16; off; off >>= 1)
            acc[e] += __shfl_xor_sync(0xffffffffu, acc[e], off);
    }
    if (lane == 0) {
        float mx = acc[0];
#pragma unroll
        for (int e = 1; e < E_NUM; e++) mx = fmaxf(mx, acc[e]);
        float p[E_NUM], s = 0.f;
#pragma unroll
        for (int e = 0; e < E_NUM; e++) { p[e] = expf(acc[e] - mx); s += p[e]; }
        float inv = 1.f / s;
#pragma unroll
        for (int e = 0; e < E_NUM; e++) p[e] *= inv;
        int e0 = 0;
#pragma unroll
        for (int e = 1; e < E_NUM; e++) if (p[e] > p[e0]) e0 = e;
        int e1 = (e0 == 0) ? 1 : 0;
#pragma unroll
        for (int e = 0; e < E_NUM; e++)
            if (e != e0 && e != e1 && p[e] > p[e1]) e1 = e;
        int pos0 = atomicAdd(&g_counts[e0], 1);
        g_bucket_tok[e0 * N_TOK + pos0] = warp * 2 + 0;
        g_bucket_scr[e0 * N_TOK + pos0] = p[e0];
        int pos1 = atomicAdd(&g_counts[e1], 1);
        g_bucket_tok[e1 * N_TOK + pos1] = warp * 2 + 1;
        g_bucket_scr[e1 * N_TOK + pos1] = p[e1];
    }
}

// ---------------- mma helpers ------------------------------------------------
#define MMA_BF16(c, a, b0, b1)                                                  \
    asm volatile(                                                               \
        "mma.sync.aligned.m16n8k16.row.col.f32.bf16.bf16.f32 "                  \
        "{%0,%1,%2,%3},{%4,%5,%6,%7},{%8,%9},{%0,%1,%2,%3};"                    \
        : "+f"((c)[0]), "+f"((c)[1]), "+f"((c)[2]), "+f"((c)[3])                \
        : "r"((a)[0]), "r"((a)[1]), "r"((a)[2]), "r"((a)[3]),                   \
          "r"(b0), "r"(b1))

__device__ __forceinline__ uint32_t bpk(const __nv_bfloat16* p, int i0, int i1) {
    uint32_t lo = *(const unsigned short*)&p[i0];
    uint32_t hi = *(const unsigned short*)&p[i1];
    return lo | (hi << 16);
}

// SMEM strides (halves)
#define SAK 40   // A tile row stride: 32 + 8 pad
#define SBN 72   // B tile row stride: 64 + 8 pad

// ---------------- fused gate+up GEMM (bf16x3) + SiLU -------------------------
// CTA tile 128(M) x 64(N), K-chunk 32, 256 threads = 8 warps (4x2 of 32x32).
template <bool ROUTED>
__global__ void __launch_bounds__(256, 2) k_gateup_mma() {
    __shared__ __nv_bfloat16 sAh[128 * SAK], sAl[128 * SAK];
    __shared__ __nv_bfloat16 sBgh[32 * SBN], sBgl[32 * SBN];
    __shared__ __nv_bfloat16 sBuh[32 * SBN], sBul[32 * SBN];

    const int e    = ROUTED ? blockIdx.z : 0;
    const int M    = ROUTED ? g_counts[e] : N_TOK;
    const int row0 = blockIdx.x * 128;
    if (row0 >= M) return;
    const int col0 = blockIdx.y * 64;

    size_t boff = ROUTED ? (size_t)e * D_DIM * H_DIM : 0;
    const __nv_bfloat16* Bgh = (ROUTED ? g_Wgh : g_sgh) + boff;
    const __nv_bfloat16* Bgl = (ROUTED ? g_Wgl : g_sgl) + boff;
    const __nv_bfloat16* Buh = (ROUTED ? g_Wuh : g_suh) + boff;
    const __nv_bfloat16* Bul = (ROUTED ? g_Wul : g_sul) + boff;

    const int tid = threadIdx.x, wid = tid >> 5, lane = tid & 31;
    const int lr = lane >> 2, lc = lane & 3;
    const int wm = (wid & 3) * 32, wn = (wid >> 2) * 32;

    // A loader mapping: thread covers rows rt and rt+64, 16B piece ro
    const int rt = tid >> 2, ro = tid & 3;
    int tokA[2]; bool valA[2];
#pragma unroll
    for (int p = 0; p < 2; p++) {
        int r = row0 + rt + p * 64;
        valA[p] = r < M;
        tokA[p] = ROUTED ? (valA[p] ? (g_bucket_tok[e * N_TOK + r] >> 1) : 0)
                         : (valA[p] ? r : 0);
    }
    const int bk = tid >> 3, bo = tid & 7;   // B loader: k row, 16B piece

    float accg[2][4][4] = {}, accu[2][4][4] = {};

    for (int k0 = 0; k0 < D_DIM; k0 += 32) {
#pragma unroll
        for (int p = 0; p < 2; p++) {
            uint4 vh = make_uint4(0, 0, 0, 0), vl = vh;
            if (valA[p]) {
                size_t gb = (size_t)tokA[p] * D_DIM + k0 + ro * 8;
                vh = *(const uint4*)(g_xh + gb);
                vl = *(const uint4*)(g_xl + gb);
            }
            int sb = (rt + p * 64) * SAK + ro * 8;
            *(uint4*)&sAh[sb] = vh;
            *(uint4*)&sAl[sb] = vl;
        }
        {
            size_t gb = (size_t)(k0 + bk) * H_DIM + col0 + bo * 8;
            int sb = bk * SBN + bo * 8;
            *(uint4*)&sBgh[sb] = *(const uint4*)(Bgh + gb);
            *(uint4*)&sBgl[sb] = *(const uint4*)(Bgl + gb);
            *(uint4*)&sBuh[sb] = *(const uint4*)(Buh + gb);
            *(uint4*)&sBul[sb] = *(const uint4*)(Bul + gb);
        }
        __syncthreads();

#pragma unroll
        for (int ks = 0; ks < 32; ks += 16) {
            uint32_t aH[2][4], aL[2][4];
#pragma unroll
            for (int mt = 0; mt < 2; mt++) {
                int base = (wm + mt * 16 + lr) * SAK + ks + lc * 2;
                aH[mt][0] = *(const uint32_t*)&sAh[base];
                aH[mt][1] = *(const uint32_t*)&sAh[base + 8 * SAK];
                aH[mt][2] = *(const uint32_t*)&sAh[base + 8];
                aH[mt][3] = *(const uint32_t*)&sAh[base + 8 * SAK + 8];
                aL[mt][0] = *(const uint32_t*)&sAl[base];
                aL[mt][1] = *(const uint32_t*)&sAl[base + 8 * SAK];
                aL[mt][2] = *(const uint32_t*)&sAl[base + 8];
                aL[mt][3] = *(const uint32_t*)&sAl[base + 8 * SAK + 8];
            }
#pragma unroll
            for (int nt = 0; nt < 4; nt++) {
                int nb = wn + nt * 8 + lr;
                int kb = ks + lc * 2;
                uint32_t bgh0 = bpk(sBgh, kb * SBN + nb, (kb + 1) * SBN + nb);
                uint32_t bgh1 = bpk(sBgh, (kb + 8) * SBN + nb, (kb + 9) * SBN + nb);
                uint32_t bgl0 = bpk(sBgl, kb * SBN + nb, (kb + 1) * SBN + nb);
                uint32_t bgl1 = bpk(sBgl, (kb + 8) * SBN + nb, (kb + 9) * SBN + nb);
                uint32_t buh0 = bpk(sBuh, kb * SBN + nb, (kb + 1) * SBN + nb);
                uint32_t buh1 = bpk(sBuh, (kb + 8) * SBN + nb, (kb + 9) * SBN + nb);
                uint32_t bul0 = bpk(sBul, kb * SBN + nb, (kb + 1) * SBN + nb);
                uint32_t bul1 = bpk(sBul, (kb + 8) * SBN + nb, (kb + 9) * SBN + nb);
#pragma unroll
                for (int mt = 0; mt < 2; mt++) {
                    MMA_BF16(accg[mt][nt], aH[mt], bgh0, bgh1);
                    MMA_BF16(accg[mt][nt], aH[mt], bgl0, bgl1);
                    MMA_BF16(accg[mt][nt], aL[mt], bgh0, bgh1);
                    MMA_BF16(accu[mt][nt], aH[mt], buh0, buh1);
                    MMA_BF16(accu[mt][nt], aH[mt], bul0, bul1);
                    MMA_BF16(accu[mt][nt], aL[mt], buh0, buh1);
                }
            }
        }
        __syncthreads();
    }

    // epilogue: h = silu(g)*u, split to bf16 hi/lo
    __nv_bfloat16* Dh = ROUTED ? g_hrh : g_h1h;
    __nv_bfloat16* Dl = ROUTED ? g_hrl : g_h1l;
#pragma unroll
    for (int mt = 0; mt < 2; mt++) {
#pragma unroll
        for (int hh = 0; hh < 2; hh++) {
            int r = row0 + wm + mt * 16 + lr + hh * 8;
            if (r >= M) continue;
            int orow = ROUTED ? g_bucket_tok[e * N_TOK + r] : r;
            size_t cb = (size_t)orow * H_DIM + col0 + wn;
#pragma unroll
            for (int nt = 0; nt < 4; nt++) {
                float gg0 = accg[mt][nt][hh * 2], gg1 = accg[mt][nt][hh * 2 + 1];
                float uu0 = accu[mt][nt][hh * 2], uu1 = accu[mt][nt][hh * 2 + 1];
                float h0 = (gg0 / (1.f + expf(-gg0))) * uu0;
                float h1 = (gg1 / (1.f + expf(-gg1))) * uu1;
                __nv_bfloat16 h0h = __float2bfloat16(h0);
                __nv_bfloat16 h1h = __float2bfloat16(h1);
                __nv_bfloat16 h0l = __float2bfloat16(h0 - __bfloat162float(h0h));
                __nv_bfloat16 h1l = __float2bfloat16(h1 - __bfloat162float(h1h));
                __nv_bfloat162 vh; vh.x = h0h; vh.y = h1h;
                __nv_bfloat162 vl; vl.x = h0l; vl.y = h1l;
                *(__nv_bfloat162*)&Dh[cb + nt * 8 + lc * 2] = vh;
                *(__nv_bfloat162*)&Dl[cb + nt * 8 + lc * 2] = vl;
            }
        }
    }
}

// ---------------- down-proj GEMM (bf16x3) ------------------------------------
template <bool ROUTED>
__global__ void __launch_bounds__(256, 2) k_down_mma(float* __restrict__ Out) {
    __shared__ __nv_bfloat16 sAh[128 * SAK], sAl[128 * SAK];
    __shared__ __nv_bfloat16 sBh[32 * SBN], sBl[32 * SBN];

    const int e    = ROUTED ? blockIdx.z : 0;
    const int M    = ROUTED ? g_counts[e] : N_TOK;
    const int row0 = blockIdx.x * 128;
    if (row0 >= M) return;
    const int col0 = blockIdx.y * 64;

    size_t boff = ROUTED ? (size_t)e * H_DIM * D_DIM : 0;
    const __nv_bfloat16* Bh = (ROUTED ? g_Wdh : g_sdh) + boff;
    const __nv_bfloat16* Bl = (ROUTED ? g_Wdl : g_sdl) + boff;
    const __nv_bfloat16* Ah = ROUTED ? g_hrh : g_h1h;
    const __nv_bfloat16* Al = ROUTED ? g_hrl : g_h1l;

    const int tid = threadIdx.x, wid = tid >> 5, lane = tid & 31;
    const int lr = lane >> 2, lc = lane & 3;
    const int wm = (wid & 3) * 32, wn = (wid >> 2) * 32;

    const int rt = tid >> 2, ro = tid & 3;
    int tokA[2]; bool valA[2];
#pragma unroll
    for (int p = 0; p < 2; p++) {
        int r = row0 + rt + p * 64;
        valA[p] = r < M;
        tokA[p] = ROUTED ? (valA[p] ? g_bucket_tok[e * N_TOK + r] : 0)
                         : (valA[p] ? r : 0);
    }
    const int bk = tid >> 3, bo = tid & 7;

    float acc[2][4][4] = {};

    for (int k0 = 0; k0 < H_DIM; k0 += 32) {
#pragma unroll
        for (int p = 0; p < 2; p++) {
            uint4 vh = make_uint4(0, 0, 0, 0), vl = vh;
            if (valA[p]) {
                size_t gb = (size_t)tokA[p] * H_DIM + k0 + ro * 8;
                vh = *(const uint4*)(Ah + gb);
                vl = *(const uint4*)(Al + gb);
            }
            int sb = (rt + p * 64) * SAK + ro * 8;
            *(uint4*)&sAh[sb] = vh;
            *(uint4*)&sAl[sb] = vl;
        }
        {
            size_t gb = (size_t)(k0 + bk) * D_DIM + col0 + bo * 8;
            int sb = bk * SBN + bo * 8;
            *(uint4*)&sBh[sb] = *(const uint4*)(Bh + gb);
            *(uint4*)&sBl[sb] = *(const uint4*)(Bl + gb);
        }
        __syncthreads();

#pragma unroll
        for (int ks = 0; ks < 32; ks += 16) {
            uint32_t aH[2][4], aL[2][4];
#pragma unroll
            for (int mt = 0; mt < 2; mt++) {
                int base = (wm + mt * 16 + lr) * SAK + ks + lc * 2;
                aH[mt][0] = *(const uint32_t*)&sAh[base];
                aH[mt][1] = *(const uint32_t*)&sAh[base + 8 * SAK];
                aH[mt][2] = *(const uint32_t*)&sAh[base + 8];
                aH[mt][3] = *(const uint32_t*)&sAh[base + 8 * SAK + 8];
                aL[mt][0] = *(const uint32_t*)&sAl[base];
                aL[mt][1] = *(const uint32_t*)&sAl[base + 8 * SAK];
                aL[mt][2] = *(const uint32_t*)&sAl[base + 8];
                aL[mt][3] = *(const uint32_t*)&sAl[base + 8 * SAK + 8];
            }
#pragma unroll
            for (int nt = 0; nt < 4; nt++) {
                int nb = wn + nt * 8 + lr;
                int kb = ks + lc * 2;
                uint32_t bh0 = bpk(sBh, kb * SBN + nb, (kb + 1) * SBN + nb);
                uint32_t bh1 = bpk(sBh, (kb + 8) * SBN + nb, (kb + 9) * SBN + nb);
                uint32_t bl0 = bpk(sBl, kb * SBN + nb, (kb + 1) * SBN + nb);
                uint32_t bl1 = bpk(sBl, (kb + 8) * SBN + nb, (kb + 9) * SBN + nb);
#pragma unroll
                for (int mt = 0; mt < 2; mt++) {
                    MMA_BF16(acc[mt][nt], aH[mt], bh0, bh1);
                    MMA_BF16(acc[mt][nt], aH[mt], bl0, bl1);
                    MMA_BF16(acc[mt][nt], aL[mt], bh0, bh1);
                }
            }
        }
        __syncthreads();
    }

#pragma unroll
    for (int mt = 0; mt < 2; mt++) {
#pragma unroll
        for (int hh = 0; hh < 2; hh++) {
            int r = row0 + wm + mt * 16 + lr + hh * 8;
            if (r >= M) continue;
            float scr = 1.f;
            size_t obase;
            float* optr;
            if (ROUTED) {
                int tok2 = g_bucket_tok[e * N_TOK + r];
                scr   = g_bucket_scr[e * N_TOK + r];
                obase = (size_t)tok2 * D_DIM;
                optr  = g_yb;
            } else {
                obase = (size_t)r * D_DIM;
                optr  = Out;
            }
#pragma unroll
            for (int nt = 0; nt < 4; nt++) {
                float2 v;
                v.x = scr * acc[mt][nt][hh * 2];
                v.y = scr * acc[mt][nt][hh * 2 + 1];
                *(float2*)&optr[obase + col0 + wn + nt * 8 + lc * 2] = v;
            }
        }
    }
}

// ---------------- final combine ---------------------------------------------
__global__ void __launch_bounds__(256) k_final(float* __restrict__ Out) {
    int i = (blockIdx.x * blockDim.x + threadIdx.x) * 4;
    if (i >= N_TOK * D_DIM) return;
    int n = i / D_DIM, d = i % D_DIM;
    float4 o  = *(float4*)(Out + i);
    float4 y0 = *(const float4*)(g_yb + (size_t)(2 * n) * D_DIM + d);
    float4 y1 = *(const float4*)(g_yb + (size_t)(2 * n + 1) * D_DIM + d);
    o.x += y0.x + y1.x;
    o.y += y0.y + y1.y;
    o.z += y0.z + y1.z;
    o.w += y0.w + y1.w;
    *(float4*)(Out + i) = o;
}

// ---------------- launch -----------------------------------------------------
extern "C" void kernel_launch(void* const* d_in, const int* in_sizes, int n_in,
                              void* d_out, int out_size) {
    const float* x           = (const float*)d_in[0];
    const float* router      = (const float*)d_in[1];
    const float* shared_gate = (const float*)d_in[2];
    const float* shared_up   = (const float*)d_in[3];
    const float* shared_down = (const float*)d_in[4];
    const float* W_gate      = (const float*)d_in[5];
    const float* W_up        = (const float*)d_in[6];
    const float* W_down      = (const float*)d_in[7];
    float* out = (float*)d_out;
    (void)in_sizes; (void)n_in; (void)out_size;

    k_reset<<<1, 32>>>();
    k_router<<<N_TOK / 8, 256>>>(x, router);

    auto split = [](const float* p, int which, int n) {
        k_split<<<(n + 255) / 256, 256>>>(p, which, n);
    };
    split(x,           0, N_TOK * D_DIM);
    split(shared_gate, 1, D_DIM * H_DIM);
    split(shared_up,   2, D_DIM * H_DIM);
    split(shared_down, 3, H_DIM * D_DIM);
    split(W_gate,      4, E_NUM * D_DIM * H_DIM);
    split(W_up,        5, E_NUM * D_DIM * H_DIM);
    split(W_down,      6, E_NUM * H_DIM * D_DIM);

    // shared expert gate+up, then routed gate+up
    {
        dim3 g(N_TOK / 128, H_DIM / 64, 1);
        k_gateup_mma<false><<<g, 256>>>();
    }
    {
        dim3 g(N_TOK / 128, H_DIM / 64, E_NUM);
        k_gateup_mma<true><<<g, 256>>>();
    }
    // down projections
    {
        dim3 g(N_TOK / 128, D_DIM / 64, 1);
        k_down_mma<false><<<g, 256>>>(out);
    }
    {
        dim3 g(N_TOK / 128, D_DIM / 64, E_NUM);
        k_down_mma<true><<<g, 256>>>(out);
    }

    k_final<<<(N_TOK * D_DIM / 4 + 255) / 256, 256>>>(out);
}

// round 6
// speedup vs baseline: 1.9986x; 1.2384x over previous
#include <cuda_runtime.h>
#include <cuda_bf16.h>
#include <math.h>
#include <stdint.h>

#define N_TOK 4096
#define D_DIM 512
#define E_NUM 8
#define H_DIM 256

// ---------------- scratch (static device globals; no allocation) -------------
__device__ int   g_counts[E_NUM];
__device__ int   g_bucket_tok[E_NUM * N_TOK];   // packed tok*2 + slot
__device__ float g_bucket_scr[E_NUM * N_TOK];

// bf16 hi/lo splits
__device__ __nv_bfloat16 g_xh[N_TOK * D_DIM],  g_xl[N_TOK * D_DIM];
__device__ __nv_bfloat16 g_sgh[D_DIM * H_DIM], g_sgl[D_DIM * H_DIM];
__device__ __nv_bfloat16 g_suh[D_DIM * H_DIM], g_sul[D_DIM * H_DIM];
__device__ __nv_bfloat16 g_sdh[H_DIM * D_DIM], g_sdl[H_DIM * D_DIM];
__device__ __nv_bfloat16 g_Wgh[E_NUM * D_DIM * H_DIM], g_Wgl[E_NUM * D_DIM * H_DIM];
__device__ __nv_bfloat16 g_Wuh[E_NUM * D_DIM * H_DIM], g_Wul[E_NUM * D_DIM * H_DIM];
__device__ __nv_bfloat16 g_Wdh[E_NUM * H_DIM * D_DIM], g_Wdl[E_NUM * H_DIM * D_DIM];
// hidden activations (split for next GEMM)
__device__ __nv_bfloat16 g_h1h[N_TOK * H_DIM], g_h1l[N_TOK * H_DIM];
__device__ __nv_bfloat16 g_hrh[N_TOK * 2 * H_DIM], g_hrl[N_TOK * 2 * H_DIM];
// routed down-proj output rows (fp32)
__device__ float g_yb[N_TOK * 2 * D_DIM];

// ---------------- reset ------------------------------------------------------
__global__ void k_reset() {
    if (threadIdx.x < E_NUM) g_counts[threadIdx.x] = 0;
}

// ---------------- fused fp32 -> bf16 hi/lo split (all tensors, one launch) ----
// float4-vectorized; region boundaries in float4 units.
#define SPL_X   524288
#define SPL_SG  557056
#define SPL_SU  589824
#define SPL_SD  622592
#define SPL_WG  884736
#define SPL_WU  1146880
#define SPL_TOT 1409024

__global__ void __launch_bounds__(256) k_split_all(
    const float* __restrict__ x,  const float* __restrict__ sg,
    const float* __restrict__ su, const float* __restrict__ sd,
    const float* __restrict__ wg, const float* __restrict__ wu,
    const float* __restrict__ wd) {
    int i = blockIdx.x * blockDim.x + threadIdx.x;   // float4 index
    if (i >= SPL_TOT) return;
    const float* src; __nv_bfloat16 *dh, *dl; int base;
    if (i < SPL_X)       { src = x;  dh = g_xh;  dl = g_xl;  base = 0; }
    else if (i < SPL_SG) { src = sg; dh = g_sgh; dl = g_sgl; base = SPL_X; }
    else if (i < SPL_SU) { src = su; dh = g_suh; dl = g_sul; base = SPL_SG; }
    else if (i < SPL_SD) { src = sd; dh = g_sdh; dl = g_sdl; base = SPL_SU; }
    else if (i < SPL_WG) { src = wg; dh = g_Wgh; dl = g_Wgl; base = SPL_SD; }
    else if (i < SPL_WU) { src = wu; dh = g_Wuh; dl = g_Wul; base = SPL_WG; }
    else                 { src = wd; dh = g_Wdh; dl = g_Wdl; base = SPL_WU; }
    int j = i - base;
    float4 v = ((const float4*)src)[j];
    float f[4] = {v.x, v.y, v.z, v.w};
    union { __nv_bfloat162 h2[2]; uint2 u; } Uh, Ul;
#pragma unroll
    for (int p = 0; p < 2; p++) {
        __nv_bfloat16 h0 = __float2bfloat16(f[p * 2 + 0]);
        __nv_bfloat16 h1 = __float2bfloat16(f[p * 2 + 1]);
        __nv_bfloat16 l0 = __float2bfloat16(f[p * 2 + 0] - __bfloat162float(h0));
        __nv_bfloat16 l1 = __float2bfloat16(f[p * 2 + 1] - __bfloat162float(h1));
        Uh.h2[p].x = h0; Uh.h2[p].y = h1;
        Ul.h2[p].x = l0; Ul.h2[p].y = l1;
    }
    *(uint2*)(dh + 4 * (size_t)j) = Uh.u;
    *(uint2*)(dl + 4 * (size_t)j) = Ul.u;
}

// ---------------- router: warp per token ------------------------------------
__global__ void __launch_bounds__(256) k_router(const float* __restrict__ x,
                                                const float* __restrict__ router) {
    int warp = (blockIdx.x * blockDim.x + threadIdx.x) >> 5;
    int lane = threadIdx.x & 31;
    if (warp >= N_TOK) return;
    const float* xr = x + (size_t)warp * D_DIM;
    float acc[E_NUM];
#pragma unroll
    for (int e = 0; e < E_NUM; e++) acc[e] = 0.f;
    for (int d = lane; d < D_DIM; d += 32) {
        float xv = xr[d];
        const float* rr = router + (size_t)d * E_NUM;
#pragma unroll
        for (int e = 0; e < E_NUM; e++) acc[e] += xv * rr[e];
    }
#pragma unroll
    for (int e = 0; e < E_NUM; e++) {
#pragma unroll
        for (int off = 16; off; off >>= 1)
            acc[e] += __shfl_xor_sync(0xffffffffu, acc[e], off);
    }
    if (lane == 0) {
        float mx = acc[0];
#pragma unroll
        for (int e = 1; e < E_NUM; e++) mx = fmaxf(mx, acc[e]);
        float p[E_NUM], s = 0.f;
#pragma unroll
        for (int e = 0; e < E_NUM; e++) { p[e] = expf(acc[e] - mx); s += p[e]; }
        float inv = 1.f / s;
#pragma unroll
        for (int e = 0; e < E_NUM; e++) p[e] *= inv;
        int e0 = 0;
#pragma unroll
        for (int e = 1; e < E_NUM; e++) if (p[e] > p[e0]) e0 = e;
        int e1 = (e0 == 0) ? 1 : 0;
#pragma unroll
        for (int e = 0; e < E_NUM; e++)
            if (e != e0 && e != e1 && p[e] > p[e1]) e1 = e;
        int pos0 = atomicAdd(&g_counts[e0], 1);
        g_bucket_tok[e0 * N_TOK + pos0] = warp * 2 + 0;
        g_bucket_scr[e0 * N_TOK + pos0] = p[e0];
        int pos1 = atomicAdd(&g_counts[e1], 1);
        g_bucket_tok[e1 * N_TOK + pos1] = warp * 2 + 1;
        g_bucket_scr[e1 * N_TOK + pos1] = p[e1];
    }
}

// ---------------- mma + ldmatrix helpers -------------------------------------
#define MMA_BF16(c, a, b0, b1)                                                  \
    asm volatile(                                                               \
        "mma.sync.aligned.m16n8k16.row.col.f32.bf16.bf16.f32 "                  \
        "{%0,%1,%2,%3},{%4,%5,%6,%7},{%8,%9},{%0,%1,%2,%3};"                    \
        : "+f"((c)[0]), "+f"((c)[1]), "+f"((c)[2]), "+f"((c)[3])                \
        : "r"((a)[0]), "r"((a)[1]), "r"((a)[2]), "r"((a)[3]),                   \
          "r"(b0), "r"(b1))

#define LDMX4(r, p)                                                             \
    asm volatile("ldmatrix.sync.aligned.m8n8.x4.shared.b16 {%0,%1,%2,%3}, [%4];"\
        : "=r"((r)[0]), "=r"((r)[1]), "=r"((r)[2]), "=r"((r)[3]) : "r"(p))

#define LDMX2T(r, p)                                                            \
    asm volatile("ldmatrix.sync.aligned.m8n8.x2.trans.shared.b16 {%0,%1}, [%2];"\
        : "=r"((r)[0]), "=r"((r)[1]) : "r"(p))

// SMEM strides (bf16 halves)
#define SAK 40   // A tile row stride: 32 + 8 pad  (80B rows: LDSM conflict-free)
#define SBN 72   // B tile row stride: 64 + 8 pad  (144B rows: LDSM conflict-free)

// ---------------- fused gate+up GEMM (bf16x3) + SiLU -------------------------
// CTA tile 128(M) x 64(N), K-chunk 32, 256 threads = 8 warps (4x2 of 32x32).
template <bool ROUTED>
__global__ void __launch_bounds__(256, 2) k_gateup_mma() {
    __shared__ __nv_bfloat16 sAh[128 * SAK], sAl[128 * SAK];
    __shared__ __nv_bfloat16 sBgh[32 * SBN], sBgl[32 * SBN];
    __shared__ __nv_bfloat16 sBuh[32 * SBN], sBul[32 * SBN];

    const int e    = ROUTED ? blockIdx.z : 0;
    const int M    = ROUTED ? g_counts[e] : N_TOK;
    const int row0 = blockIdx.x * 128;
    if (row0 >= M) return;
    const int col0 = blockIdx.y * 64;

    size_t boff = ROUTED ? (size_t)e * D_DIM * H_DIM : 0;
    const __nv_bfloat16* Bgh = (ROUTED ? g_Wgh : g_sgh) + boff;
    const __nv_bfloat16* Bgl = (ROUTED ? g_Wgl : g_sgl) + boff;
    const __nv_bfloat16* Buh = (ROUTED ? g_Wuh : g_suh) + boff;
    const __nv_bfloat16* Bul = (ROUTED ? g_Wul : g_sul) + boff;

    const int tid = threadIdx.x, wid = tid >> 5, lane = tid & 31;
    const int lr = lane >> 2, lc = lane & 3;
    const int wm = (wid & 3) * 32, wn = (wid >> 2) * 32;

    // shared-space base addresses for ldmatrix
    const uint32_t sAh_s  = (uint32_t)__cvta_generic_to_shared(sAh);
    const uint32_t sAl_s  = (uint32_t)__cvta_generic_to_shared(sAl);
    const uint32_t sBgh_s = (uint32_t)__cvta_generic_to_shared(sBgh);
    const uint32_t sBgl_s = (uint32_t)__cvta_generic_to_shared(sBgl);
    const uint32_t sBuh_s = (uint32_t)__cvta_generic_to_shared(sBuh);
    const uint32_t sBul_s = (uint32_t)__cvta_generic_to_shared(sBul);
    const int lm = lane & 15;               // ldmatrix lane row
    const int lk = (lane >> 4) << 3;        // ldmatrix A col offset

    // A loader mapping: thread covers rows rt and rt+64, 16B piece ro
    const int rt = tid >> 2, ro = tid & 3;
    int tokA[2]; bool valA[2];
#pragma unroll
    for (int p = 0; p < 2; p++) {
        int r = row0 + rt + p * 64;
        valA[p] = r < M;
        tokA[p] = ROUTED ? (valA[p] ? (g_bucket_tok[e * N_TOK + r] >> 1) : 0)
                         : (valA[p] ? r : 0);
    }
    const int bk = tid >> 3, bo = tid & 7;   // B loader: k row, 16B piece

    float accg[2][4][4] = {}, accu[2][4][4] = {};

    for (int k0 = 0; k0 < D_DIM; k0 += 32) {
#pragma unroll
        for (int p = 0; p < 2; p++) {
            uint4 vh = make_uint4(0, 0, 0, 0), vl = vh;
            if (valA[p]) {
                size_t gb = (size_t)tokA[p] * D_DIM + k0 + ro * 8;
                vh = *(const uint4*)(g_xh + gb);
                vl = *(const uint4*)(g_xl + gb);
            }
            int sb = (rt + p * 64) * SAK + ro * 8;
            *(uint4*)&sAh[sb] = vh;
            *(uint4*)&sAl[sb] = vl;
        }
        {
            size_t gb = (size_t)(k0 + bk) * H_DIM + col0 + bo * 8;
            int sb = bk * SBN + bo * 8;
            *(uint4*)&sBgh[sb] = *(const uint4*)(Bgh + gb);
            *(uint4*)&sBgl[sb] = *(const uint4*)(Bgl + gb);
            *(uint4*)&sBuh[sb] = *(const uint4*)(Buh + gb);
            *(uint4*)&sBul[sb] = *(const uint4*)(Bul + gb);
        }
        __syncthreads();

#pragma unroll
        for (int ks = 0; ks < 32; ks += 16) {
            uint32_t aH[2][4], aL[2][4];
#pragma unroll
            for (int mt = 0; mt < 2; mt++) {
                uint32_t aoff = ((wm + mt * 16 + lm) * SAK + ks + lk) * 2;
                LDMX4(aH[mt], sAh_s + aoff);
                LDMX4(aL[mt], sAl_s + aoff);
            }
#pragma unroll
            for (int nt = 0; nt < 4; nt++) {
                uint32_t bofs = ((ks + lm) * SBN + wn + nt * 8) * 2;
                uint32_t bgh[2], bgl[2], buh[2], bul[2];
                LDMX2T(bgh, sBgh_s + bofs);
                LDMX2T(bgl, sBgl_s + bofs);
                LDMX2T(buh, sBuh_s + bofs);
                LDMX2T(bul, sBul_s + bofs);
#pragma unroll
                for (int mt = 0; mt < 2; mt++) {
                    MMA_BF16(accg[mt][nt], aH[mt], bgh[0], bgh[1]);
                    MMA_BF16(accg[mt][nt], aH[mt], bgl[0], bgl[1]);
                    MMA_BF16(accg[mt][nt], aL[mt], bgh[0], bgh[1]);
                    MMA_BF16(accu[mt][nt], aH[mt], buh[0], buh[1]);
                    MMA_BF16(accu[mt][nt], aH[mt], bul[0], bul[1]);
                    MMA_BF16(accu[mt][nt], aL[mt], buh[0], buh[1]);
                }
            }
        }
        __syncthreads();
    }

    // epilogue: h = silu(g)*u, split to bf16 hi/lo
    __nv_bfloat16* Dh = ROUTED ? g_hrh : g_h1h;
    __nv_bfloat16* Dl = ROUTED ? g_hrl : g_h1l;
#pragma unroll
    for (int mt = 0; mt < 2; mt++) {
#pragma unroll
        for (int hh = 0; hh < 2; hh++) {
            int r = row0 + wm + mt * 16 + lr + hh * 8;
            if (r >= M) continue;
            int orow = ROUTED ? g_bucket_tok[e * N_TOK + r] : r;
            size_t cb = (size_t)orow * H_DIM + col0 + wn;
#pragma unroll
            for (int nt = 0; nt < 4; nt++) {
                float gg0 = accg[mt][nt][hh * 2], gg1 = accg[mt][nt][hh * 2 + 1];
                float uu0 = accu[mt][nt][hh * 2], uu1 = accu[mt][nt][hh * 2 + 1];
                float h0 = (gg0 / (1.f + expf(-gg0))) * uu0;
                float h1 = (gg1 / (1.f + expf(-gg1))) * uu1;
                __nv_bfloat16 h0h = __float2bfloat16(h0);
                __nv_bfloat16 h1h = __float2bfloat16(h1);
                __nv_bfloat16 h0l = __float2bfloat16(h0 - __bfloat162float(h0h));
                __nv_bfloat16 h1l = __float2bfloat16(h1 - __bfloat162float(h1h));
                __nv_bfloat162 vh; vh.x = h0h; vh.y = h1h;
                __nv_bfloat162 vl; vl.x = h0l; vl.y = h1l;
                *(__nv_bfloat162*)&Dh[cb + nt * 8 + lc * 2] = vh;
                *(__nv_bfloat162*)&Dl[cb + nt * 8 + lc * 2] = vl;
            }
        }
    }
}

// ---------------- down-proj GEMM (bf16x3) ------------------------------------
template <bool ROUTED>
__global__ void __launch_bounds__(256, 2) k_down_mma(float* __restrict__ Out) {
    __shared__ __nv_bfloat16 sAh[128 * SAK], sAl[128 * SAK];
    __shared__ __nv_bfloat16 sBh[32 * SBN], sBl[32 * SBN];

    const int e    = ROUTED ? blockIdx.z : 0;
    const int M    = ROUTED ? g_counts[e] : N_TOK;
    const int row0 = blockIdx.x * 128;
    if (row0 >= M) return;
    const int col0 = blockIdx.y * 64;

    size_t boff = ROUTED ? (size_t)e * H_DIM * D_DIM : 0;
    const __nv_bfloat16* Bh = (ROUTED ? g_Wdh : g_sdh) + boff;
    const __nv_bfloat16* Bl = (ROUTED ? g_Wdl : g_sdl) + boff;
    const __nv_bfloat16* Ah = ROUTED ? g_hrh : g_h1h;
    const __nv_bfloat16* Al = ROUTED ? g_hrl : g_h1l;

    const int tid = threadIdx.x, wid = tid >> 5, lane = tid & 31;
    const int lr = lane >> 2, lc = lane & 3;
    const int wm = (wid & 3) * 32, wn = (wid >> 2) * 32;

    const uint32_t sAh_s = (uint32_t)__cvta_generic_to_shared(sAh);
    const uint32_t sAl_s = (uint32_t)__cvta_generic_to_shared(sAl);
    const uint32_t sBh_s = (uint32_t)__cvta_generic_to_shared(sBh);
    const uint32_t sBl_s = (uint32_t)__cvta_generic_to_shared(sBl);
    const int lm = lane & 15;
    const int lk = (lane >> 4) << 3;

    const int rt = tid >> 2, ro = tid & 3;
    int tokA[2]; bool valA[2];
#pragma unroll
    for (int p = 0; p < 2; p++) {
        int r = row0 + rt + p * 64;
        valA[p] = r < M;
        tokA[p] = ROUTED ? (valA[p] ? g_bucket_tok[e * N_TOK + r] : 0)
                         : (valA[p] ? r : 0);
    }
    const int bk = tid >> 3, bo = tid & 7;

    float acc[2][4][4] = {};

    for (int k0 = 0; k0 < H_DIM; k0 += 32) {
#pragma unroll
        for (int p = 0; p < 2; p++) {
            uint4 vh = make_uint4(0, 0, 0, 0), vl = vh;
            if (valA[p]) {
                size_t gb = (size_t)tokA[p] * H_DIM + k0 + ro * 8;
                vh = *(const uint4*)(Ah + gb);
                vl = *(const uint4*)(Al + gb);
            }
            int sb = (rt + p * 64) * SAK + ro * 8;
            *(uint4*)&sAh[sb] = vh;
            *(uint4*)&sAl[sb] = vl;
        }
        {
            size_t gb = (size_t)(k0 + bk) * D_DIM + col0 + bo * 8;
            int sb = bk * SBN + bo * 8;
            *(uint4*)&sBh[sb] = *(const uint4*)(Bh + gb);
            *(uint4*)&sBl[sb] = *(const uint4*)(Bl + gb);
        }
        __syncthreads();

#pragma unroll
        for (int ks = 0; ks < 32; ks += 16) {
            uint32_t aH[2][4], aL[2][4];
#pragma unroll
            for (int mt = 0; mt < 2; mt++) {
                uint32_t aoff = ((wm + mt * 16 + lm) * SAK + ks + lk) * 2;
                LDMX4(aH[mt], sAh_s + aoff);
                LDMX4(aL[mt], sAl_s + aoff);
            }
#pragma unroll
            for (int nt = 0; nt < 4; nt++) {
                uint32_t bofs = ((ks + lm) * SBN + wn + nt * 8) * 2;
                uint32_t bh[2], bl[2];
                LDMX2T(bh, sBh_s + bofs);
                LDMX2T(bl, sBl_s + bofs);
#pragma unroll
                for (int mt = 0; mt < 2; mt++) {
                    MMA_BF16(acc[mt][nt], aH[mt], bh[0], bh[1]);
                    MMA_BF16(acc[mt][nt], aH[mt], bl[0], bl[1]);
                    MMA_BF16(acc[mt][nt], aL[mt], bh[0], bh[1]);
                }
            }
        }
        __syncthreads();
    }

#pragma unroll
    for (int mt = 0; mt < 2; mt++) {
#pragma unroll
        for (int hh = 0; hh < 2; hh++) {
            int r = row0 + wm + mt * 16 + lr + hh * 8;
            if (r >= M) continue;
            float scr = 1.f;
            size_t obase;
            float* optr;
            if (ROUTED) {
                int tok2 = g_bucket_tok[e * N_TOK + r];
                scr   = g_bucket_scr[e * N_TOK + r];
                obase = (size_t)tok2 * D_DIM;
                optr  = g_yb;
            } else {
                obase = (size_t)r * D_DIM;
                optr  = Out;
            }
#pragma unroll
            for (int nt = 0; nt < 4; nt++) {
                float2 v;
                v.x = scr * acc[mt][nt][hh * 2];
                v.y = scr * acc[mt][nt][hh * 2 + 1];
                *(float2*)&optr[obase + col0 + wn + nt * 8 + lc * 2] = v;
            }
        }
    }
}

// ---------------- final combine ---------------------------------------------
__global__ void __launch_bounds__(256) k_final(float* __restrict__ Out) {
    int i = (blockIdx.x * blockDim.x + threadIdx.x) * 4;
    if (i >= N_TOK * D_DIM) return;
    int n = i / D_DIM, d = i % D_DIM;
    float4 o  = *(float4*)(Out + i);
    float4 y0 = *(const float4*)(g_yb + (size_t)(2 * n) * D_DIM + d);
    float4 y1 = *(const float4*)(g_yb + (size_t)(2 * n + 1) * D_DIM + d);
    o.x += y0.x + y1.x;
    o.y += y0.y + y1.y;
    o.z += y0.z + y1.z;
    o.w += y0.w + y1.w;
    *(float4*)(Out + i) = o;
}

// ---------------- launch -----------------------------------------------------
extern "C" void kernel_launch(void* const* d_in, const int* in_sizes, int n_in,
                              void* d_out, int out_size) {
    const float* x           = (const float*)d_in[0];
    const float* router      = (const float*)d_in[1];
    const float* shared_gate = (const float*)d_in[2];
    const float* shared_up   = (const float*)d_in[3];
    const float* shared_down = (const float*)d_in[4];
    const float* W_gate      = (const float*)d_in[5];
    const float* W_up        = (const float*)d_in[6];
    const float* W_down      = (const float*)d_in[7];
    float* out = (float*)d_out;
    (void)in_sizes; (void)n_in; (void)out_size;

    k_reset<<<1, 32>>>();
    k_router<<<N_TOK / 8, 256>>>(x, router);

    k_split_all<<<SPL_TOT / 256, 256>>>(x, shared_gate, shared_up, shared_down,
                                        W_gate, W_up, W_down);

    // gate+up
    {
        dim3 g(N_TOK / 128, H_DIM / 64, 1);
        k_gateup_mma<false><<<g, 256>>>();
    }
    {
        dim3 g(N_TOK / 128, H_DIM / 64, E_NUM);
        k_gateup_mma<true><<<g, 256>>>();
    }
    // down projections
    {
        dim3 g(N_TOK / 128, D_DIM / 64, 1);
        k_down_mma<false><<<g, 256>>>(out);
    }
    {
        dim3 g(N_TOK / 128, D_DIM / 64, E_NUM);
        k_down_mma<true><<<g, 256>>>(out);
    }

    k_final<<<(N_TOK * D_DIM / 4 + 255) / 256, 256>>>(out);
}

// round 8
// speedup vs baseline: 2.1995x; 1.1005x over previous
#include <cuda_runtime.h>
#include <cuda_bf16.h>
#include <math.h>
#include <stdint.h>

#define N_TOK 4096
#define D_DIM 512
#define E_NUM 8
#define H_DIM 256

// ---------------- scratch (static device globals; no allocation) -------------
__device__ int   g_counts[E_NUM];
__device__ int   g_bucket_tok[E_NUM * N_TOK];   // packed tok*2 + slot
__device__ float g_bucket_scr[E_NUM * N_TOK];

// bf16 hi/lo splits
__device__ __nv_bfloat16 g_xh[N_TOK * D_DIM],  g_xl[N_TOK * D_DIM];
__device__ __nv_bfloat16 g_sgh[D_DIM * H_DIM], g_sgl[D_DIM * H_DIM];
__device__ __nv_bfloat16 g_suh[D_DIM * H_DIM], g_sul[D_DIM * H_DIM];
__device__ __nv_bfloat16 g_sdh[H_DIM * D_DIM], g_sdl[H_DIM * D_DIM];
__device__ __nv_bfloat16 g_Wgh[E_NUM * D_DIM * H_DIM], g_Wgl[E_NUM * D_DIM * H_DIM];
__device__ __nv_bfloat16 g_Wuh[E_NUM * D_DIM * H_DIM], g_Wul[E_NUM * D_DIM * H_DIM];
__device__ __nv_bfloat16 g_Wdh[E_NUM * H_DIM * D_DIM], g_Wdl[E_NUM * H_DIM * D_DIM];
// hidden activations (split for next GEMM)
__device__ __nv_bfloat16 g_h1h[N_TOK * H_DIM], g_h1l[N_TOK * H_DIM];
__device__ __nv_bfloat16 g_hrh[N_TOK * 2 * H_DIM], g_hrl[N_TOK * 2 * H_DIM];
// routed down-proj output rows (fp32)
__device__ float g_yb[N_TOK * 2 * D_DIM];

// ---------------- reset ------------------------------------------------------
__global__ void k_reset() {
    if (threadIdx.x < E_NUM) g_counts[threadIdx.x] = 0;
}

// ---------------- fused fp32 -> bf16 hi/lo split (all tensors, one launch) ----
#define SPL_X   524288
#define SPL_SG  557056
#define SPL_SU  589824
#define SPL_SD  622592
#define SPL_WG  884736
#define SPL_WU  1146880
#define SPL_TOT 1409024

__global__ void __launch_bounds__(256) k_split_all(
    const float* __restrict__ x,  const float* __restrict__ sg,
    const float* __restrict__ su, const float* __restrict__ sd,
    const float* __restrict__ wg, const float* __restrict__ wu,
    const float* __restrict__ wd) {
    int i = blockIdx.x * blockDim.x + threadIdx.x;   // float4 index
    if (i >= SPL_TOT) return;
    const float* src; __nv_bfloat16 *dh, *dl; int base;
    if (i < SPL_X)       { src = x;  dh = g_xh;  dl = g_xl;  base = 0; }
    else if (i < SPL_SG) { src = sg; dh = g_sgh; dl = g_sgl; base = SPL_X; }
    else if (i < SPL_SU) { src = su; dh = g_suh; dl = g_sul; base = SPL_SG; }
    else if (i < SPL_SD) { src = sd; dh = g_sdh; dl = g_sdl; base = SPL_SU; }
    else if (i < SPL_WG) { src = wg; dh = g_Wgh; dl = g_Wgl; base = SPL_SD; }
    else if (i < SPL_WU) { src = wu; dh = g_Wuh; dl = g_Wul; base = SPL_WG; }
    else                 { src = wd; dh = g_Wdh; dl = g_Wdl; base = SPL_WU; }
    int j = i - base;
    float4 v = ((const float4*)src)[j];
    float f[4] = {v.x, v.y, v.z, v.w};
    union { __nv_bfloat162 h2[2]; uint2 u; } Uh, Ul;
#pragma unroll
    for (int p = 0; p < 2; p++) {
        __nv_bfloat16 h0 = __float2bfloat16(f[p * 2 + 0]);
        __nv_bfloat16 h1 = __float2bfloat16(f[p * 2 + 1]);
        __nv_bfloat16 l0 = __float2bfloat16(f[p * 2 + 0] - __bfloat162float(h0));
        __nv_bfloat16 l1 = __float2bfloat16(f[p * 2 + 1] - __bfloat162float(h1));
        Uh.h2[p].x = h0; Uh.h2[p].y = h1;
        Ul.h2[p].x = l0; Ul.h2[p].y = l1;
    }
    *(uint2*)(dh + 4 * (size_t)j) = Uh.u;
    *(uint2*)(dl + 4 * (size_t)j) = Ul.u;
}

// ---------------- router: warp per token ------------------------------------
__global__ void __launch_bounds__(256) k_router(const float* __restrict__ x,
                                                const float* __restrict__ router) {
    int warp = (blockIdx.x * blockDim.x + threadIdx.x) >> 5;
    int lane = threadIdx.x & 31;
    if (warp >= N_TOK) return;
    const float* xr = x + (size_t)warp * D_DIM;
    float acc[E_NUM];
#pragma unroll
    for (int e = 0; e < E_NUM; e++) acc[e] = 0.f;
    for (int d = lane; d < D_DIM; d += 32) {
        float xv = xr[d];
        const float* rr = router + (size_t)d * E_NUM;
#pragma unroll
        for (int e = 0; e < E_NUM; e++) acc[e] += xv * rr[e];
    }
#pragma unroll
    for (int e = 0; e < E_NUM; e++) {
#pragma unroll
        for (int off = 16; off; off >>= 1)
            acc[e] += __shfl_xor_sync(0xffffffffu, acc[e], off);
    }
    if (lane == 0) {
        float mx = acc[0];
#pragma unroll
        for (int e = 1; e < E_NUM; e++) mx = fmaxf(mx, acc[e]);
        float p[E_NUM], s = 0.f;
#pragma unroll
        for (int e = 0; e < E_NUM; e++) { p[e] = expf(acc[e] - mx); s += p[e]; }
        float inv = 1.f / s;
#pragma unroll
        for (int e = 0; e < E_NUM; e++) p[e] *= inv;
        int e0 = 0;
#pragma unroll
        for (int e = 1; e < E_NUM; e++) if (p[e] > p[e0]) e0 = e;
        int e1 = (e0 == 0) ? 1 : 0;
#pragma unroll
        for (int e = 0; e < E_NUM; e++)
            if (e != e0 && e != e1 && p[e] > p[e1]) e1 = e;
        int pos0 = atomicAdd(&g_counts[e0], 1);
        g_bucket_tok[e0 * N_TOK + pos0] = warp * 2 + 0;
        g_bucket_scr[e0 * N_TOK + pos0] = p[e0];
        int pos1 = atomicAdd(&g_counts[e1], 1);
        g_bucket_tok[e1 * N_TOK + pos1] = warp * 2 + 1;
        g_bucket_scr[e1 * N_TOK + pos1] = p[e1];
    }
}

// ---------------- mma / ldmatrix / cp.async helpers ---------------------------
#define MMA_BF16(c, a, b0, b1)                                                  \
    asm volatile(                                                               \
        "mma.sync.aligned.m16n8k16.row.col.f32.bf16.bf16.f32 "                  \
        "{%0,%1,%2,%3},{%4,%5,%6,%7},{%8,%9},{%0,%1,%2,%3};"                    \
        : "+f"((c)[0]), "+f"((c)[1]), "+f"((c)[2]), "+f"((c)[3])                \
        : "r"((a)[0]), "r"((a)[1]), "r"((a)[2]), "r"((a)[3]),                   \
          "r"(b0), "r"(b1))

#define LDMX4(r, p)                                                             \
    asm volatile("ldmatrix.sync.aligned.m8n8.x4.shared.b16 {%0,%1,%2,%3}, [%4];"\
        : "=r"((r)[0]), "=r"((r)[1]), "=r"((r)[2]), "=r"((r)[3]) : "r"(p))

#define LDMX2T(r, p)                                                            \
    asm volatile("ldmatrix.sync.aligned.m8n8.x2.trans.shared.b16 {%0,%1}, [%2];"\
        : "=r"((r)[0]), "=r"((r)[1]) : "r"(p))

#define CP16(dst, src, valid) do {                                              \
    int _sz = (valid) ? 16 : 0;                                                 \
    asm volatile("cp.async.cg.shared.global [%0], [%1], 16, %2;"                \
        :: "r"(dst), "l"(src), "r"(_sz));                                       \
} while (0)
#define CP_COMMIT() asm volatile("cp.async.commit_group;" ::: "memory")
#define CP_WAIT1()  asm volatile("cp.async.wait_group 1;" ::: "memory")
#define CP_WAIT0()  asm volatile("cp.async.wait_group 0;" ::: "memory")

// SMEM strides (bf16 elements)
#define SAK 40   // A tile row stride: 32 + 8 pad
#define SBN 72   // B tile row stride: 64 + 8 pad
// per-stage sizes (elements)
#define A_ST 5120          // 128*SAK
#define B_ST 2304          // 32*SBN
// gate+up smem layout (elements): Ah[2]|Al[2]|Bgh[2]|Bgl[2]|Buh[2]|Bul[2]
#define GU_AL_OFF   10240
#define GU_B_OFF    20480
#define GU_SMEM_EL  38912
#define GU_SMEM_B   (GU_SMEM_EL * 2)
// down smem layout: Ah[2]|Al[2]|Bh[2]|Bl[2]
#define DN_B_OFF    20480
#define DN_SMEM_EL  29696
#define DN_SMEM_B   (DN_SMEM_EL * 2)

// ---------------- fused gate+up GEMM (bf16x3) + SiLU --------------------------
// z==0: shared expert; z>=1: routed expert z-1. CTA 128x64, 2-stage cp.async.
__global__ void __launch_bounds__(256, 2) k_gateup_mma() {
    extern __shared__ __align__(16) __nv_bfloat16 smem[];

    const int z  = blockIdx.z;
    const bool SH = (z == 0);
    const int e  = SH ? 0 : z - 1;
    const int M  = SH ? N_TOK : g_counts[e];
    const int row0 = blockIdx.x * 128;
    if (row0 >= M) return;
    const int col0 = blockIdx.y * 64;

    size_t boff = SH ? 0 : (size_t)e * D_DIM * H_DIM;
    const __nv_bfloat16* Bgh = (SH ? g_sgh : g_Wgh) + boff;
    const __nv_bfloat16* Bgl = (SH ? g_sgl : g_Wgl) + boff;
    const __nv_bfloat16* Buh = (SH ? g_suh : g_Wuh) + boff;
    const __nv_bfloat16* Bul = (SH ? g_sul : g_Wul) + boff;

    const int tid = threadIdx.x, wid = tid >> 5, lane = tid & 31;
    const int lr = lane >> 2, lc = lane & 3;
    const int wm = (wid & 3) * 32, wn = (wid >> 2) * 32;

    const uint32_t sb = (uint32_t)__cvta_generic_to_shared(smem);
    const int lm = lane & 15;
    const int lk = (lane >> 4) << 3;

    const int rt = tid >> 2, ro = tid & 3;
    int tokA[2]; bool valA[2];
#pragma unroll
    for (int p = 0; p < 2; p++) {
        int r = row0 + rt + p * 64;
        valA[p] = r < M;
        tokA[p] = SH ? (valA[p] ? r : 0)
                     : (valA[p] ? (g_bucket_tok[e * N_TOK + r] >> 1) : 0);
    }
    const int bk = tid >> 3, bo = tid & 7;

    float accg[2][4][4] = {}, accu[2][4][4] = {};

    // prefetch helper (issues 8 cp.async of 16B per thread)
    auto LOADC = [&](int s, int k0) {
#pragma unroll
        for (int p = 0; p < 2; p++) {
            size_t ga = (size_t)tokA[p] * D_DIM + k0 + ro * 8;
            uint32_t d = sb + (uint32_t)(s * A_ST + (rt + p * 64) * SAK + ro * 8) * 2;
            CP16(d,                g_xh + ga, valA[p]);
            CP16(d + GU_AL_OFF * 2, g_xl + ga, valA[p]);
        }
        size_t gb = (size_t)(k0 + bk) * H_DIM + col0 + bo * 8;
        uint32_t db = sb + (uint32_t)(GU_B_OFF + s * B_ST + bk * SBN + bo * 8) * 2;
        CP16(db,                 Bgh + gb, true);
        CP16(db + 2 * B_ST * 2,  Bgl + gb, true);
        CP16(db + 4 * B_ST * 2,  Buh + gb, true);
        CP16(db + 6 * B_ST * 2,  Bul + gb, true);
    };

    const int NC = D_DIM / 32;   // 16
    LOADC(0, 0);
    CP_COMMIT();

    for (int c = 0; c < NC; c++) {
        if (c + 1 < NC) {
            LOADC((c + 1) & 1, (c + 1) * 32);
            CP_COMMIT();
            CP_WAIT1();
        } else {
            CP_WAIT0();
        }
        __syncthreads();

        const int s = c & 1;
        const uint32_t aBase  = sb + (uint32_t)(s * A_ST) * 2;
        const uint32_t bBase  = sb + (uint32_t)(GU_B_OFF + s * B_ST) * 2;
#pragma unroll
        for (int ks = 0; ks < 32; ks += 16) {
            uint32_t aH[2][4], aL[2][4];
#pragma unroll
            for (int mt = 0; mt < 2; mt++) {
                uint32_t aoff = aBase + (uint32_t)((wm + mt * 16 + lm) * SAK + ks + lk) * 2;
                LDMX4(aH[mt], aoff);
                LDMX4(aL[mt], aoff + GU_AL_OFF * 2);
            }
#pragma unroll
            for (int nt = 0; nt < 4; nt++) {
                uint32_t bofs = bBase + (uint32_t)((ks + lm) * SBN + wn + nt * 8) * 2;
                uint32_t bgh[2], bgl[2], buh[2], bul[2];
                LDMX2T(bgh, bofs);
                LDMX2T(bgl, bofs + 2 * B_ST * 2);
                LDMX2T(buh, bofs + 4 * B_ST * 2);
                LDMX2T(bul, bofs + 6 * B_ST * 2);
#pragma unroll
                for (int mt = 0; mt < 2; mt++) {
                    MMA_BF16(accg[mt][nt], aH[mt], bgh[0], bgh[1]);
                    MMA_BF16(accg[mt][nt], aH[mt], bgl[0], bgl[1]);
                    MMA_BF16(accg[mt][nt], aL[mt], bgh[0], bgh[1]);
                    MMA_BF16(accu[mt][nt], aH[mt], buh[0], buh[1]);
                    MMA_BF16(accu[mt][nt], aH[mt], bul[0], bul[1]);
                    MMA_BF16(accu[mt][nt], aL[mt], buh[0], buh[1]);
                }
            }
        }
        __syncthreads();
    }

    // epilogue: h = silu(g)*u, split to bf16 hi/lo
    __nv_bfloat16* Dh = SH ? g_h1h : g_hrh;
    __nv_bfloat16* Dl = SH ? g_h1l : g_hrl;
#pragma unroll
    for (int mt = 0; mt < 2; mt++) {
#pragma unroll
        for (int hh = 0; hh < 2; hh++) {
            int r = row0 + wm + mt * 16 + lr + hh * 8;
            if (r >= M) continue;
            int orow = SH ? r : g_bucket_tok[e * N_TOK + r];
            size_t cb = (size_t)orow * H_DIM + col0 + wn;
#pragma unroll
            for (int nt = 0; nt < 4; nt++) {
                float gg0 = accg[mt][nt][hh * 2], gg1 = accg[mt][nt][hh * 2 + 1];
                float uu0 = accu[mt][nt][hh * 2], uu1 = accu[mt][nt][hh * 2 + 1];
                float h0 = (gg0 / (1.f + expf(-gg0))) * uu0;
                float h1 = (gg1 / (1.f + expf(-gg1))) * uu1;
                __nv_bfloat16 h0h = __float2bfloat16(h0);
                __nv_bfloat16 h1h = __float2bfloat16(h1);
                __nv_bfloat16 h0l = __float2bfloat16(h0 - __bfloat162float(h0h));
                __nv_bfloat16 h1l = __float2bfloat16(h1 - __bfloat162float(h1h));
                __nv_bfloat162 vh; vh.x = h0h; vh.y = h1h;
                __nv_bfloat162 vl; vl.x = h0l; vl.y = h1l;
                *(__nv_bfloat162*)&Dh[cb + nt * 8 + lc * 2] = vh;
                *(__nv_bfloat162*)&Dl[cb + nt * 8 + lc * 2] = vl;
            }
        }
    }
}

// ---------------- down-proj GEMM (bf16x3) -------------------------------------
__global__ void __launch_bounds__(256, 2) k_down_mma(float* __restrict__ Out) {
    extern __shared__ __align__(16) __nv_bfloat16 smem[];

    const int z  = blockIdx.z;
    const bool SH = (z == 0);
    const int e  = SH ? 0 : z - 1;
    const int M  = SH ? N_TOK : g_counts[e];
    const int row0 = blockIdx.x * 128;
    if (row0 >= M) return;
    const int col0 = blockIdx.y * 64;

    size_t boff = SH ? 0 : (size_t)e * H_DIM * D_DIM;
    const __nv_bfloat16* Bh = (SH ? g_sdh : g_Wdh) + boff;
    const __nv_bfloat16* Bl = (SH ? g_sdl : g_Wdl) + boff;
    const __nv_bfloat16* Ah = SH ? g_h1h : g_hrh;
    const __nv_bfloat16* Al = SH ? g_h1l : g_hrl;

    const int tid = threadIdx.x, wid = tid >> 5, lane = tid & 31;
    const int lr = lane >> 2, lc = lane & 3;
    const int wm = (wid & 3) * 32, wn = (wid >> 2) * 32;

    const uint32_t sb = (uint32_t)__cvta_generic_to_shared(smem);
    const int lm = lane & 15;
    const int lk = (lane >> 4) << 3;

    const int rt = tid >> 2, ro = tid & 3;
    int tokA[2]; bool valA[2];
#pragma unroll
    for (int p = 0; p < 2; p++) {
        int r = row0 + rt + p * 64;
        valA[p] = r < M;
        tokA[p] = SH ? (valA[p] ? r : 0)
                     : (valA[p] ? g_bucket_tok[e * N_TOK + r] : 0);
    }
    const int bk = tid >> 3, bo = tid & 7;

    float acc[2][4][4] = {};

    auto LOADC = [&](int s, int k0) {
#pragma unroll
        for (int p = 0; p < 2; p++) {
            size_t ga = (size_t)tokA[p] * H_DIM + k0 + ro * 8;
            uint32_t d = sb + (uint32_t)(s * A_ST + (rt + p * 64) * SAK + ro * 8) * 2;
            CP16(d,                 Ah + ga, valA[p]);
            CP16(d + GU_AL_OFF * 2, Al + ga, valA[p]);
        }
        size_t gb = (size_t)(k0 + bk) * D_DIM + col0 + bo * 8;
        uint32_t db = sb + (uint32_t)(DN_B_OFF + s * B_ST + bk * SBN + bo * 8) * 2;
        CP16(db,                Bh + gb, true);
        CP16(db + 2 * B_ST * 2, Bl + gb, true);
    };

    const int NC = H_DIM / 32;   // 8
    LOADC(0, 0);
    CP_COMMIT();

    for (int c = 0; c < NC; c++) {
        if (c + 1 < NC) {
            LOADC((c + 1) & 1, (c + 1) * 32);
            CP_COMMIT();
            CP_WAIT1();
        } else {
            CP_WAIT0();
        }
        __syncthreads();

        const int s = c & 1;
        const uint32_t aBase = sb + (uint32_t)(s * A_ST) * 2;
        const uint32_t bBase = sb + (uint32_t)(DN_B_OFF + s * B_ST) * 2;
#pragma unroll
        for (int ks = 0; ks < 32; ks += 16) {
            uint32_t aH[2][4], aL[2][4];
#pragma unroll
            for (int mt = 0; mt < 2; mt++) {
                uint32_t aoff = aBase + (uint32_t)((wm + mt * 16 + lm) * SAK + ks + lk) * 2;
                LDMX4(aH[mt], aoff);
                LDMX4(aL[mt], aoff + GU_AL_OFF * 2);
            }
#pragma unroll
            for (int nt = 0; nt < 4; nt++) {
                uint32_t bofs = bBase + (uint32_t)((ks + lm) * SBN + wn + nt * 8) * 2;
                uint32_t bh[2], bl[2];
                LDMX2T(bh, bofs);
                LDMX2T(bl, bofs + 2 * B_ST * 2);
#pragma unroll
                for (int mt = 0; mt < 2; mt++) {
                    MMA_BF16(acc[mt][nt], aH[mt], bh[0], bh[1]);
                    MMA_BF16(acc[mt][nt], aH[mt], bl[0], bl[1]);
                    MMA_BF16(acc[mt][nt], aL[mt], bh[0], bh[1]);
                }
            }
        }
        __syncthreads();
    }

#pragma unroll
    for (int mt = 0; mt < 2; mt++) {
#pragma unroll
        for (int hh = 0; hh < 2; hh++) {
            int r = row0 + wm + mt * 16 + lr + hh * 8;
            if (r >= M) continue;
            float scr = 1.f;
            size_t obase;
            float* optr;
            if (!SH) {
                int tok2 = g_bucket_tok[e * N_TOK + r];
                scr   = g_bucket_scr[e * N_TOK + r];
                obase = (size_t)tok2 * D_DIM;
                optr  = g_yb;
            } else {
                obase = (size_t)r * D_DIM;
                optr  = Out;
            }
#pragma unroll
            for (int nt = 0; nt < 4; nt++) {
                float2 v;
                v.x = scr * acc[mt][nt][hh * 2];
                v.y = scr * acc[mt][nt][hh * 2 + 1];
                *(float2*)&optr[obase + col0 + wn + nt * 8 + lc * 2] = v;
            }
        }
    }
}

// ---------------- final combine ---------------------------------------------
__global__ void __launch_bounds__(256) k_final(float* __restrict__ Out) {
    int i = (blockIdx.x * blockDim.x + threadIdx.x) * 4;
    if (i >= N_TOK * D_DIM) return;
    int n = i / D_DIM, d = i % D_DIM;
    float4 o  = *(float4*)(Out + i);
    float4 y0 = *(const float4*)(g_yb + (size_t)(2 * n) * D_DIM + d);
    float4 y1 = *(const float4*)(g_yb + (size_t)(2 * n + 1) * D_DIM + d);
    o.x += y0.x + y1.x;
    o.y += y0.y + y1.y;
    o.z += y0.z + y1.z;
    o.w += y0.w + y1.w;
    *(float4*)(Out + i) = o;
}

// ---------------- launch -----------------------------------------------------
extern "C" void kernel_launch(void* const* d_in, const int* in_sizes, int n_in,
                              void* d_out, int out_size) {
    const float* x           = (const float*)d_in[0];
    const float* router      = (const float*)d_in[1];
    const float* shared_gate = (const float*)d_in[2];
    const float* shared_up   = (const float*)d_in[3];
    const float* shared_down = (const float*)d_in[4];
    const float* W_gate      = (const float*)d_in[5];
    const float* W_up        = (const float*)d_in[6];
    const float* W_down      = (const float*)d_in[7];
    float* out = (float*)d_out;
    (void)in_sizes; (void)n_in; (void)out_size;

    cudaFuncSetAttribute(k_gateup_mma,
                         cudaFuncAttributeMaxDynamicSharedMemorySize, GU_SMEM_B);
    cudaFuncSetAttribute(k_down_mma,
                         cudaFuncAttributeMaxDynamicSharedMemorySize, DN_SMEM_B);

    k_reset<<<1, 32>>>();
    k_router<<<N_TOK / 8, 256>>>(x, router);

    k_split_all<<<SPL_TOT / 256, 256>>>(x, shared_gate, shared_up, shared_down,
                                        W_gate, W_up, W_down);

    // fused shared+routed gate+up (z=0 shared, z=1..8 experts)
    {
        dim3 g(N_TOK / 128, H_DIM / 64, E_NUM + 1);
        k_gateup_mma<<<g, 256, GU_SMEM_B>>>();
    }
    // fused shared+routed down-proj
    {
        dim3 g(N_TOK / 128, D_DIM / 64, E_NUM + 1);
        k_down_mma<<<g, 256, DN_SMEM_B>>>(out);
    }

    k_final<<<(N_TOK * D_DIM / 4 + 255) / 256, 256>>>(out);
}